// round 3
// baseline (speedup 1.0000x reference)
#include <cuda_runtime.h>

// MetapathGATConv fused kernel, R2: register-blocked GEMM (4 cols x 8 rows / thread),
// f32x2 FMA packed along k. One CTA = 8 nodes; all intermediates in SMEM.

#define RREL   8
#define EMBED  256
#define NB     8            // nodes per CTA
#define ROWS   (NB * RREL)  // 64
#define PITCH  260          // SMEM row pitch (floats), 16B-aligned rows
#define NTHREADS 512

typedef unsigned long long ull;

__device__ __forceinline__ ull packf2(float lo, float hi) {
    ull r;
    asm("mov.b64 %0, {%1, %2};" : "=l"(r) : "f"(lo), "f"(hi));
    return r;
}
__device__ __forceinline__ void unpackf2(ull v, float& lo, float& hi) {
    asm("mov.b64 {%0, %1}, %2;" : "=f"(lo), "=f"(hi) : "l"(v));
}
__device__ __forceinline__ void fma2(ull& d, ull a, ull b) {
    asm("fma.rn.f32x2 %0, %1, %2, %0;" : "+l"(d) : "l"(a), "l"(b));
}
__device__ __forceinline__ float hsum2(ull v) {
    float lo, hi; unpackf2(v, lo, hi); return lo + hi;
}
__device__ __forceinline__ float leaky(float v) {
    return v > 0.f ? v : 0.2f * v;
}

// C[row, cg*4+c] = sum_k A[row,k] * W[k*256 + cg*4+c] + bias[cg*4+c]
// Each thread: NR rows (rbase + r*RSTEP) x 4 adjacent cols (cg*4..cg*4+3).
// A,C in SMEM (PITCH); W,bias in global (L2-resident).
// Accumulators are f32x2 packed along k (even-k in lo, odd-k in hi).
template <int NR, int RSTEP>
__device__ __forceinline__ void gemm_rb(
    const float* __restrict__ W, const float* __restrict__ bias,
    const float* __restrict__ A, float* __restrict__ C,
    int cg, int rbase)
{
    const float4* __restrict__ W4 = reinterpret_cast<const float4*>(W);

    ull acc[NR][4];
#pragma unroll
    for (int r = 0; r < NR; r++)
#pragma unroll
        for (int c = 0; c < 4; c++) acc[r][c] = 0ull;

    // prefetch first W chunk (4 k-rows x 4 cols)
    float4 w0 = W4[0 * 64 + cg];
    float4 w1 = W4[1 * 64 + cg];
    float4 w2 = W4[2 * 64 + cg];
    float4 w3 = W4[3 * 64 + cg];

#pragma unroll 2
    for (int k = 0; k < EMBED; k += 4) {
        // pack W pairs along k: (W[k][c], W[k+1][c]) and (W[k+2][c], W[k+3][c])
        ull wk01[4], wk23[4];
        wk01[0] = packf2(w0.x, w1.x); wk01[1] = packf2(w0.y, w1.y);
        wk01[2] = packf2(w0.z, w1.z); wk01[3] = packf2(w0.w, w1.w);
        wk23[0] = packf2(w2.x, w3.x); wk23[1] = packf2(w2.y, w3.y);
        wk23[2] = packf2(w2.z, w3.z); wk23[3] = packf2(w2.w, w3.w);

        if (k + 4 < EMBED) {   // prefetch next chunk
            w0 = W4[(k + 4) * 64 + cg];
            w1 = W4[(k + 5) * 64 + cg];
            w2 = W4[(k + 6) * 64 + cg];
            w3 = W4[(k + 7) * 64 + cg];
        }

#pragma unroll
        for (int r = 0; r < NR; r++) {
            const ulonglong2 av = *reinterpret_cast<const ulonglong2*>(
                A + (rbase + r * RSTEP) * PITCH + k);   // (A[k],A[k+1]) | (A[k+2],A[k+3])
#pragma unroll
            for (int c = 0; c < 4; c++) {
                fma2(acc[r][c], av.x, wk01[c]);
                fma2(acc[r][c], av.y, wk23[c]);
            }
        }
    }

    const float4 b4 = reinterpret_cast<const float4*>(bias)[cg];
#pragma unroll
    for (int r = 0; r < NR; r++) {
        float4 o;
        o.x = hsum2(acc[r][0]) + b4.x;
        o.y = hsum2(acc[r][1]) + b4.y;
        o.z = hsum2(acc[r][2]) + b4.z;
        o.w = hsum2(acc[r][3]) + b4.w;
        *reinterpret_cast<float4*>(&C[(rbase + r * RSTEP) * PITCH + cg * 4]) = o;
    }
}

extern "C" __global__ void __launch_bounds__(NTHREADS, 1)
metapath_gat_kernel(
    const float* __restrict__ x,
    const float* __restrict__ Wl0, const float* __restrict__ bl0,
    const float* __restrict__ Wr0, const float* __restrict__ br0,
    const float* __restrict__ att0, const float* __restrict__ bias0,
    const float* __restrict__ Wl1, const float* __restrict__ bl1,
    const float* __restrict__ Wr1, const float* __restrict__ br1,
    const float* __restrict__ att1, const float* __restrict__ bias1,
    float* __restrict__ outEmb, float* __restrict__ outBeta)
{
    extern __shared__ float smem[];
    float* bufH   = smem;                      // [64][260]  h0 then h1
    float* bufXL  = bufH + ROWS * PITCH;       // [64][260]  xl0 then xl1
    float* bufXR  = bufXL + ROWS * PITCH;      // [64][260]  xr0 then xr1(self rows)
    float* alphaS = bufXR + ROWS * PITCH;      // [8][8][8][4] = 2048
    float* betaS  = alphaS + 2048;             // [8][8][4]   = 256
    float* attS   = betaS + 256;               // att0 | att1 = 512

    const int tid = threadIdx.x;
    const int g = blockIdx.x;
    const float* xg = x + (size_t)g * (NB * RREL * EMBED);

    if (tid < 512) attS[tid] = (tid < 256) ? att0[tid] : att1[tid - 256];

    // ---- Phase 1: load x -> relu -> bufH ----
#pragma unroll
    for (int i = 0; i < 8; i++) {
        int idx = tid + i * NTHREADS;          // 0..4095 float4s
        float4 v = reinterpret_cast<const float4*>(xg)[idx];
        int f = idx * 4;
        int r = f >> 8;
        int d = f & 255;
        v.x = fmaxf(v.x, 0.f); v.y = fmaxf(v.y, 0.f);
        v.z = fmaxf(v.z, 0.f); v.w = fmaxf(v.w, 0.f);
        *reinterpret_cast<float4*>(&bufH[r * PITCH + d]) = v;
    }
    __syncthreads();

    const int cg   = tid & 63;   // col-group: cols cg*4 .. cg*4+3
    const int rg   = tid >> 6;   // row-group: rows rg*8 .. rg*8+7 (also node id)
    const int col  = tid & 255;  // per-column mapping for epilogue phases
    const int half = tid >> 8;   // 0/1 node-halves for epilogue phases

    // ---- Phase 2: layer-0 GEMMs (xl0, xr0) ----
    gemm_rb<8, 1>(Wl0, bl0, bufH, bufXL, cg, rg * 8);
    gemm_rb<8, 1>(Wr0, br0, bufH, bufXR, cg, rg * 8);
    __syncthreads();

    // ---- Phase 3: logits0 + softmax over j -> alphaS ----
    {
        int w = tid >> 5, lane = tid & 31;
        int node = w & 7, ihalf = w >> 3;      // warp -> (node, i-half)
        int j = lane >> 2, h = lane & 3;       // lane -> (src j, head h)
        const float* att = attS + h * 64;
        const float* xlrow = bufXL + (node * 8 + j) * PITCH + h * 64;
#pragma unroll
        for (int ii = 0; ii < 4; ii++) {
            int i = ihalf * 4 + ii;
            const float* xrrow = bufXR + (node * 8 + i) * PITCH + h * 64;
            float s = 0.f;
#pragma unroll 8
            for (int c = 0; c < 64; c++)
                s += att[c] * leaky(xrrow[c] + xlrow[c]);
            float m = s;
            m = fmaxf(m, __shfl_xor_sync(0xffffffffu, m, 4));
            m = fmaxf(m, __shfl_xor_sync(0xffffffffu, m, 8));
            m = fmaxf(m, __shfl_xor_sync(0xffffffffu, m, 16));
            float e = __expf(s - m);
            float sum = e;
            sum += __shfl_xor_sync(0xffffffffu, sum, 4);
            sum += __shfl_xor_sync(0xffffffffu, sum, 8);
            sum += __shfl_xor_sync(0xffffffffu, sum, 16);
            alphaS[((node * 8 + i) * 8 + j) * 4 + h] = e / sum;
        }
    }
    __syncthreads();

    // ---- Phase 4: aggregate h1 = relu(alpha @ xl0 + bias0) -> bufH ----
    {
        int h = col >> 6;
        float b0 = bias0[col];
#pragma unroll
        for (int nn = 0; nn < 4; nn++) {
            int nd = half * 4 + nn;
            float xlv[8];
#pragma unroll
            for (int j = 0; j < 8; j++) xlv[j] = bufXL[(nd * 8 + j) * PITCH + col];
#pragma unroll
            for (int i = 0; i < 8; i++) {
                float s = b0;
#pragma unroll
                for (int j = 0; j < 8; j++)
                    s += alphaS[((nd * 8 + i) * 8 + j) * 4 + h] * xlv[j];
                bufH[(nd * 8 + i) * PITCH + col] = fmaxf(s, 0.f);
            }
        }
    }
    __syncthreads();

    // ---- Phase 5: layer-1 GEMMs: xl1 -> bufXL; xr1(self rows rg*8+7) -> bufXR ----
    gemm_rb<8, 1>(Wl1, bl1, bufH, bufXL, cg, rg * 8);
    gemm_rb<1, 1>(Wr1, br1, bufH, bufXR, cg, rg * 8 + 7);
    __syncthreads();

    // ---- Phase 6: logits1 + softmax over r -> beta (smem + global) ----
    if (tid < 256) {
        int node = tid >> 5, lane = tid & 31;
        int r = lane >> 2, h = lane & 3;
        const float* att = attS + 256 + h * 64;
        const float* xr = bufXR + (node * 8 + 7) * PITCH + h * 64;
        const float* xl = bufXL + (node * 8 + r) * PITCH + h * 64;
        float s = 0.f;
#pragma unroll 8
        for (int c = 0; c < 64; c++)
            s += att[c] * leaky(xr[c] + xl[c]);
        float m = s;
        m = fmaxf(m, __shfl_xor_sync(0xffffffffu, m, 4));
        m = fmaxf(m, __shfl_xor_sync(0xffffffffu, m, 8));
        m = fmaxf(m, __shfl_xor_sync(0xffffffffu, m, 16));
        float e = __expf(s - m);
        float sum = e;
        sum += __shfl_xor_sync(0xffffffffu, sum, 4);
        sum += __shfl_xor_sync(0xffffffffu, sum, 8);
        sum += __shfl_xor_sync(0xffffffffu, sum, 16);
        float beta = e / sum;
        betaS[(node * 8 + r) * 4 + h] = beta;
        outBeta[(size_t)(g * 8 + node) * 32 + r * 4 + h] = beta;
    }
    __syncthreads();

    // ---- Phase 7: out = relu(beta @ xl1 + bias1) -> global ----
    {
        int h = col >> 6;
        float b1 = bias1[col];
#pragma unroll
        for (int nn = 0; nn < 4; nn++) {
            int nd = half * 4 + nn;
            float s = b1;
#pragma unroll
            for (int r = 0; r < 8; r++)
                s += betaS[(nd * 8 + r) * 4 + h] * bufXL[(nd * 8 + r) * PITCH + col];
            outEmb[(size_t)(g * 8 + nd) * 256 + col] = fmaxf(s, 0.f);
        }
    }
}

extern "C" void kernel_launch(void* const* d_in, const int* in_sizes, int n_in,
                              void* d_out, int out_size)
{
    const float* x     = (const float*)d_in[0];
    const float* Wl0   = (const float*)d_in[1];
    const float* bl0   = (const float*)d_in[2];
    const float* Wr0   = (const float*)d_in[3];
    const float* br0   = (const float*)d_in[4];
    const float* att0  = (const float*)d_in[5];
    const float* bias0 = (const float*)d_in[6];
    const float* Wl1   = (const float*)d_in[7];
    const float* bl1   = (const float*)d_in[8];
    const float* Wr1   = (const float*)d_in[9];
    const float* br1   = (const float*)d_in[10];
    const float* att1  = (const float*)d_in[11];
    const float* bias1 = (const float*)d_in[12];

    int nodes = in_sizes[0] / (RREL * EMBED);   // 16384
    float* outEmb  = (float*)d_out;
    float* outBeta = outEmb + (size_t)nodes * EMBED;

    size_t smem_bytes = (size_t)(3 * ROWS * PITCH + 2048 + 256 + 512) * sizeof(float);
    cudaFuncSetAttribute(metapath_gat_kernel,
                         cudaFuncAttributeMaxDynamicSharedMemorySize,
                         (int)smem_bytes);

    dim3 grid(nodes / NB);
    metapath_gat_kernel<<<grid, NTHREADS, smem_bytes>>>(
        x, Wl0, bl0, Wr0, br0, att0, bias0,
        Wl1, bl1, Wr1, br1, att1, bias1,
        outEmb, outBeta);
}

// round 7
// speedup vs baseline: 2.3456x; 2.3456x over previous
#include <cuda_runtime.h>
#include <cstdint>

// MetapathGATConv fused kernel, R3: tf32 mma.sync tensor-core GEMMs.
// One CTA = 8 nodes. W pre-packed (pre-kernel) into fragment-major tf32 in a
// static device buffer; staged into SMEM per 8-k slice via cp.async.

#define RREL   8
#define EMBED  256
#define NB     8
#define ROWS   64            // NB * RREL
#define PITCH  260           // smem row pitch (floats); 4-skew -> conflict-free frags
#define NTHREADS 512
#define KSTEPS 32            // 256 / 8
#define SLICE_F4 512         // float4 per W slice: 16 grp * 32 lane
#define WMAT_F4 (KSTEPS * SLICE_F4)   // 16384 float4 per matrix

__device__ float4 g_Wf[4 * WMAT_F4];   // Wl0 | Wr0 | Wl1 | Wr1, fragment-major tf32

// ---------------- small helpers ----------------
__device__ __forceinline__ float tf32r(float x) {
    uint32_t u;
    asm("cvt.rna.tf32.f32 %0, %1;" : "=r"(u) : "f"(x));
    return __uint_as_float(u);
}
__device__ __forceinline__ float leaky(float v) { return v > 0.f ? v : 0.2f * v; }

__device__ __forceinline__ void cp16(void* s, const void* g) {
    uint32_t sa = (uint32_t)__cvta_generic_to_shared(s);
    asm volatile("cp.async.ca.shared.global [%0], [%1], 16;" :: "r"(sa), "l"(g));
}
__device__ __forceinline__ void cp_commit() { asm volatile("cp.async.commit_group;"); }
template <int N> __device__ __forceinline__ void cp_wait() {
    asm volatile("cp.async.wait_group %0;" :: "n"(N));
}

__device__ __forceinline__ void mma_tf32(float* c, const uint32_t* a, const uint32_t* b) {
    asm volatile(
        "mma.sync.aligned.m16n8k8.row.col.f32.tf32.tf32.f32 "
        "{%0,%1,%2,%3}, {%4,%5,%6,%7}, {%8,%9}, {%0,%1,%2,%3};"
        : "+f"(c[0]), "+f"(c[1]), "+f"(c[2]), "+f"(c[3])
        : "r"(a[0]), "r"(a[1]), "r"(a[2]), "r"(a[3]), "r"(b[0]), "r"(b[1]));
}

// ---------------- W repack pre-kernel ----------------
// Fragment-major: Wf[mat][s][grp][lane] = float4(
//   W[8s+l%4][16g+l/4], W[8s+l%4+4][16g+l/4],
//   W[8s+l%4][16g+l/4+8], W[8s+l%4+4][16g+l/4+8])  (tf32-rounded)
__global__ void repack_W(const float* __restrict__ Wl0, const float* __restrict__ Wr0,
                         const float* __restrict__ Wl1, const float* __restrict__ Wr1)
{
    int idx = blockIdx.x * blockDim.x + threadIdx.x;     // 0..65535
    int m   = idx >> 14;
    int rem = idx & 16383;
    int s   = rem >> 9;
    int g   = (rem >> 5) & 15;
    int l   = rem & 31;
    const float* W = (m == 0) ? Wl0 : (m == 1) ? Wr0 : (m == 2) ? Wl1 : Wr1;
    int k0 = 8 * s + (l & 3);
    int n0 = 16 * g + (l >> 2);
    float4 f;
    f.x = tf32r(W[k0 * EMBED + n0]);
    f.y = tf32r(W[(k0 + 4) * EMBED + n0]);
    f.z = tf32r(W[k0 * EMBED + n0 + 8]);
    f.w = tf32r(W[(k0 + 4) * EMBED + n0 + 8]);
    g_Wf[idx] = f;
}

// ---------------- tensor-core GEMM over SMEM A ----------------
// Big: D[64,256] = A[64,256] @ W + bias. 16 warps = 2 Mband(32) x 8 Nband(32).
// SMALL: xr1 rows: A rows = node*8+7 (node = lane/4), only warps 0..7, D rows node*8+7.
template <bool SMALL>
__device__ __forceinline__ void gemm_tc(
    const float4* __restrict__ Wf, const float* __restrict__ bias,
    const float* __restrict__ A, float* __restrict__ D,
    float4* __restrict__ stage, int tid)
{
    const int wid = tid >> 5, lane = tid & 31;
    const int mb = wid >> 3, nb = wid & 7;
    const int qr = lane >> 2, qk = lane & 3;

    float acc[8][4];
#pragma unroll
    for (int t = 0; t < 8; t++)
#pragma unroll
        for (int j = 0; j < 4; j++) acc[t][j] = 0.f;

    // prologue: slice 0
    cp16(stage + tid, Wf + tid);
    cp_commit();

    for (int s = 0; s < KSTEPS; s++) {
        float4* cur = stage + (s & 1) * SLICE_F4;
        float4* nxt = stage + ((s + 1) & 1) * SLICE_F4;
        if (s + 1 < KSTEPS) {
            cp16(nxt + tid, Wf + (s + 1) * SLICE_F4 + tid);
            cp_commit();
            cp_wait<1>();
        } else {
            cp_wait<0>();
        }
        __syncthreads();   // slice s visible to all; prev readers of nxt done

        if (!SMALL || wid < 8) {
            uint32_t a[2][4];
            if (!SMALL) {
#pragma unroll
                for (int mt = 0; mt < 2; mt++) {
                    const float* Ar  = A + (mb * 32 + mt * 16 + qr) * PITCH + s * 8;
                    const float* Ar8 = Ar + 8 * PITCH;
                    a[mt][0] = __float_as_uint(Ar[qk]);
                    a[mt][1] = __float_as_uint(Ar8[qk]);
                    a[mt][2] = __float_as_uint(Ar[qk + 4]);
                    a[mt][3] = __float_as_uint(Ar8[qk + 4]);
                }
            } else {
                const float* Ar = A + (qr * 8 + 7) * PITCH + s * 8;
                a[0][0] = __float_as_uint(Ar[qk]);
                a[0][2] = __float_as_uint(Ar[qk + 4]);
                a[0][1] = a[0][0];          // rows 8..15 duplicated, results ignored
                a[0][3] = a[0][2];
            }
            uint32_t b[4][2];
#pragma unroll
            for (int gi = 0; gi < 2; gi++) {
                float4 f = cur[(nb * 2 + gi) * 32 + lane];
                b[2 * gi][0]     = __float_as_uint(f.x);
                b[2 * gi][1]     = __float_as_uint(f.y);
                b[2 * gi + 1][0] = __float_as_uint(f.z);
                b[2 * gi + 1][1] = __float_as_uint(f.w);
            }
            if (!SMALL) {
#pragma unroll
                for (int mt = 0; mt < 2; mt++)
#pragma unroll
                    for (int nt = 0; nt < 4; nt++) mma_tf32(acc[mt * 4 + nt], a[mt], b[nt]);
            } else {
#pragma unroll
                for (int nt = 0; nt < 4; nt++) mma_tf32(acc[nt], a[0], b[nt]);
            }
        }
        __syncthreads();   // all reads of cur done before it is refilled next iter
    }

    // epilogue: add bias, store to SMEM
    if (!SMALL) {
#pragma unroll
        for (int mt = 0; mt < 2; mt++)
#pragma unroll
            for (int nt = 0; nt < 4; nt++) {
                int row = mb * 32 + mt * 16 + qr;
                int c0  = nb * 32 + nt * 8 + 2 * qk;
                float bx = bias[c0], by = bias[c0 + 1];
                float* d = D + row * PITCH + c0;
                d[0] = acc[mt * 4 + nt][0] + bx;
                d[1] = acc[mt * 4 + nt][1] + by;
                d[8 * PITCH]     = acc[mt * 4 + nt][2] + bx;
                d[8 * PITCH + 1] = acc[mt * 4 + nt][3] + by;
            }
    } else if (wid < 8) {
#pragma unroll
        for (int nt = 0; nt < 4; nt++) {
            int c0 = nb * 32 + nt * 8 + 2 * qk;
            float* d = D + (qr * 8 + 7) * PITCH + c0;
            d[0] = acc[nt][0] + bias[c0];
            d[1] = acc[nt][1] + bias[c0 + 1];
        }
    }
}

// ---------------- main fused kernel ----------------
extern "C" __global__ void __launch_bounds__(NTHREADS, 1)
metapath_gat_kernel(
    const float* __restrict__ x,
    const float* __restrict__ bl0, const float* __restrict__ br0,
    const float* __restrict__ att0, const float* __restrict__ bias0,
    const float* __restrict__ bl1, const float* __restrict__ br1,
    const float* __restrict__ att1, const float* __restrict__ bias1,
    float* __restrict__ outEmb, float* __restrict__ outBeta)
{
    extern __shared__ float smem[];
    float*  bufH   = smem;                       // [64][260]
    float*  bufXL  = bufH + ROWS * PITCH;        // [64][260]
    float*  bufXR  = bufXL + ROWS * PITCH;       // [64][260]
    float4* stage  = (float4*)(bufXR + ROWS * PITCH);   // 2 * 512 float4
    float*  alphaS = (float*)stage + 4096;       // 2048
    float*  betaS  = alphaS + 2048;              // 256
    float*  attS   = betaS + 256;                // 512

    const int tid = threadIdx.x;
    const int g = blockIdx.x;
    const float* xg = x + (size_t)g * (NB * RREL * EMBED);

    if (tid < 512) attS[tid] = (tid < 256) ? att0[tid] : att1[tid - 256];

    // ---- Phase 1: load x -> relu -> tf32 round -> bufH ----
#pragma unroll
    for (int i = 0; i < 8; i++) {
        int idx = tid + i * NTHREADS;            // 0..4095 float4s
        float4 v = reinterpret_cast<const float4*>(xg)[idx];
        int f = idx * 4;
        int r = f >> 8;
        int d = f & 255;
        v.x = tf32r(fmaxf(v.x, 0.f)); v.y = tf32r(fmaxf(v.y, 0.f));
        v.z = tf32r(fmaxf(v.z, 0.f)); v.w = tf32r(fmaxf(v.w, 0.f));
        *reinterpret_cast<float4*>(&bufH[r * PITCH + d]) = v;
    }
    __syncthreads();

    // ---- Phase 2: layer-0 GEMMs ----
    gemm_tc<false>(g_Wf + 0 * WMAT_F4, bl0, bufH, bufXL, stage, tid);
    gemm_tc<false>(g_Wf + 1 * WMAT_F4, br0, bufH, bufXR, stage, tid);
    __syncthreads();

    const int col  = tid & 255;
    const int half = tid >> 8;

    // ---- Phase 3: logits0 + softmax over j -> alphaS ----
    {
        int w = tid >> 5, lane = tid & 31;
        int node = w & 7, ihalf = w >> 3;
        int j = lane >> 2, h = lane & 3;
        const float* att = attS + h * 64;
        const float* xlrow = bufXL + (node * 8 + j) * PITCH + h * 64;
#pragma unroll
        for (int ii = 0; ii < 4; ii++) {
            int i = ihalf * 4 + ii;
            const float* xrrow = bufXR + (node * 8 + i) * PITCH + h * 64;
            float s = 0.f;
#pragma unroll 8
            for (int c = 0; c < 64; c++)
                s += att[c] * leaky(xrrow[c] + xlrow[c]);
            float m = s;
            m = fmaxf(m, __shfl_xor_sync(0xffffffffu, m, 4));
            m = fmaxf(m, __shfl_xor_sync(0xffffffffu, m, 8));
            m = fmaxf(m, __shfl_xor_sync(0xffffffffu, m, 16));
            float e = __expf(s - m);
            float sum = e;
            sum += __shfl_xor_sync(0xffffffffu, sum, 4);
            sum += __shfl_xor_sync(0xffffffffu, sum, 8);
            sum += __shfl_xor_sync(0xffffffffu, sum, 16);
            alphaS[((node * 8 + i) * 8 + j) * 4 + h] = e / sum;
        }
    }
    __syncthreads();

    // ---- Phase 4: h1 = relu(alpha @ xl0 + bias0) -> bufH (tf32 rounded) ----
    {
        int h = col >> 6;
        float b0 = bias0[col];
#pragma unroll
        for (int nn = 0; nn < 4; nn++) {
            int nd = half * 4 + nn;
            float xlv[8];
#pragma unroll
            for (int j = 0; j < 8; j++) xlv[j] = bufXL[(nd * 8 + j) * PITCH + col];
#pragma unroll
            for (int i = 0; i < 8; i++) {
                float s = b0;
#pragma unroll
                for (int j = 0; j < 8; j++)
                    s += alphaS[((nd * 8 + i) * 8 + j) * 4 + h] * xlv[j];
                bufH[(nd * 8 + i) * PITCH + col] = tf32r(fmaxf(s, 0.f));
            }
        }
    }
    __syncthreads();

    // ---- Phase 5: layer-1 GEMMs: xl1 -> bufXL; xr1(self rows) -> bufXR ----
    gemm_tc<false>(g_Wf + 2 * WMAT_F4, bl1, bufH, bufXL, stage, tid);
    gemm_tc<true >(g_Wf + 3 * WMAT_F4, br1, bufH, bufXR, stage, tid);
    __syncthreads();

    // ---- Phase 6: logits1 + softmax over r -> beta ----
    if (tid < 256) {
        int node = tid >> 5, lane = tid & 31;
        int r = lane >> 2, h = lane & 3;
        const float* att = attS + 256 + h * 64;
        const float* xr = bufXR + (node * 8 + 7) * PITCH + h * 64;
        const float* xl = bufXL + (node * 8 + r) * PITCH + h * 64;
        float s = 0.f;
#pragma unroll 8
        for (int c = 0; c < 64; c++)
            s += att[c] * leaky(xr[c] + xl[c]);
        float m = s;
        m = fmaxf(m, __shfl_xor_sync(0xffffffffu, m, 4));
        m = fmaxf(m, __shfl_xor_sync(0xffffffffu, m, 8));
        m = fmaxf(m, __shfl_xor_sync(0xffffffffu, m, 16));
        float e = __expf(s - m);
        float sum = e;
        sum += __shfl_xor_sync(0xffffffffu, sum, 4);
        sum += __shfl_xor_sync(0xffffffffu, sum, 8);
        sum += __shfl_xor_sync(0xffffffffu, sum, 16);
        float beta = e / sum;
        betaS[(node * 8 + r) * 4 + h] = beta;
        outBeta[(size_t)(g * 8 + node) * 32 + r * 4 + h] = beta;
    }
    __syncthreads();

    // ---- Phase 7: out = relu(beta @ xl1 + bias1) ----
    {
        int h = col >> 6;
        float b1 = bias1[col];
#pragma unroll
        for (int nn = 0; nn < 4; nn++) {
            int nd = half * 4 + nn;
            float s = b1;
#pragma unroll
            for (int r = 0; r < 8; r++)
                s += betaS[(nd * 8 + r) * 4 + h] * bufXL[(nd * 8 + r) * PITCH + col];
            outEmb[(size_t)(g * 8 + nd) * 256 + col] = fmaxf(s, 0.f);
        }
    }
}

extern "C" void kernel_launch(void* const* d_in, const int* in_sizes, int n_in,
                              void* d_out, int out_size)
{
    const float* x     = (const float*)d_in[0];
    const float* Wl0   = (const float*)d_in[1];
    const float* bl0   = (const float*)d_in[2];
    const float* Wr0   = (const float*)d_in[3];
    const float* br0   = (const float*)d_in[4];
    const float* att0  = (const float*)d_in[5];
    const float* bias0 = (const float*)d_in[6];
    const float* Wl1   = (const float*)d_in[7];
    const float* bl1   = (const float*)d_in[8];
    const float* Wr1   = (const float*)d_in[9];
    const float* br1   = (const float*)d_in[10];
    const float* att1  = (const float*)d_in[11];
    const float* bias1 = (const float*)d_in[12];

    int nodes = in_sizes[0] / (RREL * EMBED);    // 16384
    float* outEmb  = (float*)d_out;
    float* outBeta = outEmb + (size_t)nodes * EMBED;

    // pre-kernel: fragment-major tf32 repack of the 4 weight matrices
    repack_W<<<256, 256>>>(Wl0, Wr0, Wl1, Wr1);

    size_t smem_bytes = (size_t)(3 * ROWS * PITCH + 4096 + 2048 + 256 + 512) * sizeof(float);
    cudaFuncSetAttribute(metapath_gat_kernel,
                         cudaFuncAttributeMaxDynamicSharedMemorySize,
                         (int)smem_bytes);

    metapath_gat_kernel<<<nodes / NB, NTHREADS, smem_bytes>>>(
        x, bl0, br0, att0, bias0, bl1, br1, att1, bias1, outEmb, outBeta);
}

// round 8
// speedup vs baseline: 3.6344x; 1.5495x over previous
#include <cuda_runtime.h>
#include <cstdint>

// MetapathGATConv fused kernel, R4: tf32 mma.sync, fused Wl+Wr k-loops
// (A read once, 16 mma/slice), 1 barrier per slice, bank-rotated logits.

#define RREL   8
#define EMBED  256
#define NB     8
#define ROWS   64
#define PITCH  260
#define NTHREADS 512
#define KSTEPS 32
#define SLICE_F4 512
#define WMAT_F4 (KSTEPS * SLICE_F4)

__device__ float4 g_Wf[4 * WMAT_F4];   // Wl0 | Wr0 | Wl1 | Wr1, fragment-major tf32

__device__ __forceinline__ float tf32r(float x) {
    uint32_t u;
    asm("cvt.rna.tf32.f32 %0, %1;" : "=r"(u) : "f"(x));
    return __uint_as_float(u);
}
__device__ __forceinline__ float leaky(float v) { return v > 0.f ? v : 0.2f * v; }

__device__ __forceinline__ void cp16(void* s, const void* g) {
    uint32_t sa = (uint32_t)__cvta_generic_to_shared(s);
    asm volatile("cp.async.ca.shared.global [%0], [%1], 16;" :: "r"(sa), "l"(g));
}
__device__ __forceinline__ void cp_commit() { asm volatile("cp.async.commit_group;"); }
template <int N> __device__ __forceinline__ void cp_wait() {
    asm volatile("cp.async.wait_group %0;" :: "n"(N));
}

__device__ __forceinline__ void mma_tf32(float* c, const uint32_t* a, const uint32_t* b) {
    asm volatile(
        "mma.sync.aligned.m16n8k8.row.col.f32.tf32.tf32.f32 "
        "{%0,%1,%2,%3}, {%4,%5,%6,%7}, {%8,%9}, {%0,%1,%2,%3};"
        : "+f"(c[0]), "+f"(c[1]), "+f"(c[2]), "+f"(c[3])
        : "r"(a[0]), "r"(a[1]), "r"(a[2]), "r"(a[3]), "r"(b[0]), "r"(b[1]));
}

// W repack: Wf[mat][s][grp][lane] fragment-major tf32 (see R3).
__global__ void repack_W(const float* __restrict__ Wl0, const float* __restrict__ Wr0,
                         const float* __restrict__ Wl1, const float* __restrict__ Wr1)
{
    int idx = blockIdx.x * blockDim.x + threadIdx.x;
    int m   = idx >> 14;
    int rem = idx & 16383;
    int s   = rem >> 9;
    int g   = (rem >> 5) & 15;
    int l   = rem & 31;
    const float* W = (m == 0) ? Wl0 : (m == 1) ? Wr0 : (m == 2) ? Wl1 : Wr1;
    int k0 = 8 * s + (l & 3);
    int n0 = 16 * g + (l >> 2);
    float4 f;
    f.x = tf32r(W[k0 * EMBED + n0]);
    f.y = tf32r(W[(k0 + 4) * EMBED + n0]);
    f.z = tf32r(W[k0 * EMBED + n0 + 8]);
    f.w = tf32r(W[(k0 + 4) * EMBED + n0 + 8]);
    g_Wf[idx] = f;
}

// Fused dual GEMM: DL = A@Wl + biasL (staged via cp.async),
//                  DR = A@Wr + biasR (Wr streamed from L2).
// SMALL: Wr path only computes rows node*8+7 (warps 0..7), written to DR.
template <bool SMALL>
__device__ __forceinline__ void gemm_dual(
    const float4* __restrict__ WlF, const float* __restrict__ biasL,
    const float4* __restrict__ WrF, const float* __restrict__ biasR,
    const float* __restrict__ A, float* __restrict__ DL, float* __restrict__ DR,
    float4* __restrict__ stage, int tid)
{
    const int wid = tid >> 5, lane = tid & 31;
    const int mb = wid >> 3, nb = wid & 7;
    const int qr = lane >> 2, qk = lane & 3;
    const bool doSmall = !SMALL || wid < 8;

    float accL[8][4];
    float accR[8][4];
#pragma unroll
    for (int t = 0; t < 8; t++)
#pragma unroll
        for (int j = 0; j < 4; j++) { accL[t][j] = 0.f; accR[t][j] = 0.f; }

    cp16(stage + tid, WlF + tid);          // prologue: Wl slice 0
    cp_commit();

    for (int s = 0; s < KSTEPS; s++) {
        cp_wait<0>();
        __syncthreads();                   // slice s visible; prev buf free
        float4* cur = stage + (s & 1) * SLICE_F4;
        if (s + 1 < KSTEPS) {
            cp16(stage + ((s + 1) & 1) * SLICE_F4 + tid,
                 WlF + (s + 1) * SLICE_F4 + tid);
            cp_commit();
        }

        // stream Wr fragments from L2 early (latency overlaps Wl mma)
        float4 fr0, fr1;
        if (doSmall) {
            fr0 = WrF[(s * 16 + nb * 2 + 0) * 32 + lane];
            fr1 = WrF[(s * 16 + nb * 2 + 1) * 32 + lane];
        }

        // A fragments (shared by both matrices)
        uint32_t a[2][4];
#pragma unroll
        for (int mt = 0; mt < 2; mt++) {
            const float* Ar  = A + (mb * 32 + mt * 16 + qr) * PITCH + s * 8;
            const float* Ar8 = Ar + 8 * PITCH;
            a[mt][0] = __float_as_uint(Ar[qk]);
            a[mt][1] = __float_as_uint(Ar8[qk]);
            a[mt][2] = __float_as_uint(Ar[qk + 4]);
            a[mt][3] = __float_as_uint(Ar8[qk + 4]);
        }
        uint32_t as[4];
        if (SMALL) {
            const float* Ar = A + (qr * 8 + 7) * PITCH + s * 8;
            as[0] = __float_as_uint(Ar[qk]);
            as[2] = __float_as_uint(Ar[qk + 4]);
            as[1] = as[0]; as[3] = as[2];
        }

        // Wl mma (from SMEM stage)
        {
            uint32_t b[4][2];
#pragma unroll
            for (int gi = 0; gi < 2; gi++) {
                float4 f = cur[(nb * 2 + gi) * 32 + lane];
                b[2 * gi][0]     = __float_as_uint(f.x);
                b[2 * gi][1]     = __float_as_uint(f.y);
                b[2 * gi + 1][0] = __float_as_uint(f.z);
                b[2 * gi + 1][1] = __float_as_uint(f.w);
            }
#pragma unroll
            for (int mt = 0; mt < 2; mt++)
#pragma unroll
                for (int nt = 0; nt < 4; nt++) mma_tf32(accL[mt * 4 + nt], a[mt], b[nt]);
        }

        // Wr mma (from registers/L2)
        if (doSmall) {
            uint32_t b[4][2];
            b[0][0] = __float_as_uint(fr0.x); b[0][1] = __float_as_uint(fr0.y);
            b[1][0] = __float_as_uint(fr0.z); b[1][1] = __float_as_uint(fr0.w);
            b[2][0] = __float_as_uint(fr1.x); b[2][1] = __float_as_uint(fr1.y);
            b[3][0] = __float_as_uint(fr1.z); b[3][1] = __float_as_uint(fr1.w);
            if (!SMALL) {
#pragma unroll
                for (int mt = 0; mt < 2; mt++)
#pragma unroll
                    for (int nt = 0; nt < 4; nt++) mma_tf32(accR[mt * 4 + nt], a[mt], b[nt]);
            } else {
#pragma unroll
                for (int nt = 0; nt < 4; nt++) mma_tf32(accR[nt], as, b[nt]);
            }
        }
    }
    __syncthreads();   // protect stage before caller reuses (aliased alphaS)

    // epilogue
#pragma unroll
    for (int mt = 0; mt < 2; mt++)
#pragma unroll
        for (int nt = 0; nt < 4; nt++) {
            int row = mb * 32 + mt * 16 + qr;
            int c0  = nb * 32 + nt * 8 + 2 * qk;
            float bx = biasL[c0], by = biasL[c0 + 1];
            float* d = DL + row * PITCH + c0;
            d[0] = accL[mt * 4 + nt][0] + bx;
            d[1] = accL[mt * 4 + nt][1] + by;
            d[8 * PITCH]     = accL[mt * 4 + nt][2] + bx;
            d[8 * PITCH + 1] = accL[mt * 4 + nt][3] + by;
        }
    if (!SMALL) {
#pragma unroll
        for (int mt = 0; mt < 2; mt++)
#pragma unroll
            for (int nt = 0; nt < 4; nt++) {
                int row = mb * 32 + mt * 16 + qr;
                int c0  = nb * 32 + nt * 8 + 2 * qk;
                float bx = biasR[c0], by = biasR[c0 + 1];
                float* d = DR + row * PITCH + c0;
                d[0] = accR[mt * 4 + nt][0] + bx;
                d[1] = accR[mt * 4 + nt][1] + by;
                d[8 * PITCH]     = accR[mt * 4 + nt][2] + bx;
                d[8 * PITCH + 1] = accR[mt * 4 + nt][3] + by;
            }
    } else if (wid < 8) {
#pragma unroll
        for (int nt = 0; nt < 4; nt++) {
            int c0 = nb * 32 + nt * 8 + 2 * qk;
            float* d = DR + (qr * 8 + 7) * PITCH + c0;
            d[0] = accR[nt][0] + biasR[c0];
            d[1] = accR[nt][1] + biasR[c0 + 1];
        }
    }
}

extern "C" __global__ void __launch_bounds__(NTHREADS, 1)
metapath_gat_kernel(
    const float* __restrict__ x,
    const float* __restrict__ bl0, const float* __restrict__ br0,
    const float* __restrict__ att0, const float* __restrict__ bias0,
    const float* __restrict__ bl1, const float* __restrict__ br1,
    const float* __restrict__ att1, const float* __restrict__ bias1,
    float* __restrict__ outEmb, float* __restrict__ outBeta)
{
    extern __shared__ float smem[];
    float*  bufH   = smem;                              // [64][260]
    float*  bufXL  = bufH + ROWS * PITCH;               // [64][260]
    float*  bufXR  = bufXL + ROWS * PITCH;              // [64][260]
    float4* stage  = (float4*)(bufXR + ROWS * PITCH);   // 2*512 float4 (16 KB)
    float*  alphaS = (float*)stage;                     // aliased: used between GEMMs
    float*  betaS  = (float*)(stage + 2 * SLICE_F4);    // 256
    float*  attS   = betaS + 256;                       // 512

    const int tid = threadIdx.x;
    const int g = blockIdx.x;
    const float* xg = x + (size_t)g * (NB * RREL * EMBED);

    if (tid < 512) attS[tid] = (tid < 256) ? att0[tid] : att1[tid - 256];

    // Phase 1: x -> relu -> tf32 -> bufH
#pragma unroll
    for (int i = 0; i < 8; i++) {
        int idx = tid + i * NTHREADS;
        float4 v = reinterpret_cast<const float4*>(xg)[idx];
        int f = idx * 4;
        int r = f >> 8;
        int d = f & 255;
        v.x = tf32r(fmaxf(v.x, 0.f)); v.y = tf32r(fmaxf(v.y, 0.f));
        v.z = tf32r(fmaxf(v.z, 0.f)); v.w = tf32r(fmaxf(v.w, 0.f));
        *reinterpret_cast<float4*>(&bufH[r * PITCH + d]) = v;
    }
    __syncthreads();

    // Phase 2: fused layer-0 GEMMs (xl0 staged, xr0 streamed)
    gemm_dual<false>(g_Wf + 0 * WMAT_F4, bl0, g_Wf + 1 * WMAT_F4, br0,
                     bufH, bufXL, bufXR, stage, tid);
    __syncthreads();

    const int col  = tid & 255;
    const int half = tid >> 8;

    // Phase 3: logits0 + softmax over j (bank-rotated by h: conflict-free)
    {
        int w = tid >> 5, lane = tid & 31;
        int node = w & 7, ihalf = w >> 3;
        int j = lane >> 2, h = lane & 3;
        const float* att = attS + h * 64;
        const float* xlrow = bufXL + (node * 8 + j) * PITCH + h * 64;
#pragma unroll
        for (int ii = 0; ii < 4; ii++) {
            int i = ihalf * 4 + ii;
            const float* xrrow = bufXR + (node * 8 + i) * PITCH + h * 64;
            float s = 0.f;
#pragma unroll 8
            for (int c = 0; c < 64; c++) {
                int cc = (c + h) & 63;
                s += att[cc] * leaky(xrrow[cc] + xlrow[cc]);
            }
            float m = s;
            m = fmaxf(m, __shfl_xor_sync(0xffffffffu, m, 4));
            m = fmaxf(m, __shfl_xor_sync(0xffffffffu, m, 8));
            m = fmaxf(m, __shfl_xor_sync(0xffffffffu, m, 16));
            float e = __expf(s - m);
            float sum = e;
            sum += __shfl_xor_sync(0xffffffffu, sum, 4);
            sum += __shfl_xor_sync(0xffffffffu, sum, 8);
            sum += __shfl_xor_sync(0xffffffffu, sum, 16);
            alphaS[((node * 8 + i) * 8 + j) * 4 + h] = e / sum;
        }
    }
    __syncthreads();

    // Phase 4: h1 = relu(alpha @ xl0 + bias0) -> bufH (tf32)
    {
        int h = col >> 6;
        float b0 = bias0[col];
#pragma unroll
        for (int nn = 0; nn < 4; nn++) {
            int nd = half * 4 + nn;
            float xlv[8];
#pragma unroll
            for (int j = 0; j < 8; j++) xlv[j] = bufXL[(nd * 8 + j) * PITCH + col];
#pragma unroll
            for (int i = 0; i < 8; i++) {
                float s = b0;
#pragma unroll
                for (int j = 0; j < 8; j++)
                    s += alphaS[((nd * 8 + i) * 8 + j) * 4 + h] * xlv[j];
                bufH[(nd * 8 + i) * PITCH + col] = tf32r(fmaxf(s, 0.f));
            }
        }
    }
    __syncthreads();

    // Phase 5: fused layer-1 GEMMs (xl1 staged; xr1 self-rows streamed)
    gemm_dual<true>(g_Wf + 2 * WMAT_F4, bl1, g_Wf + 3 * WMAT_F4, br1,
                    bufH, bufXL, bufXR, stage, tid);
    __syncthreads();

    // Phase 6: logits1 + softmax over r -> beta (rotated, conflict-free)
    if (tid < 256) {
        int node = tid >> 5, lane = tid & 31;
        int r = lane >> 2, h = lane & 3;
        const float* att = attS + 256 + h * 64;
        const float* xr = bufXR + (node * 8 + 7) * PITCH + h * 64;
        const float* xl = bufXL + (node * 8 + r) * PITCH + h * 64;
        float s = 0.f;
#pragma unroll 8
        for (int c = 0; c < 64; c++) {
            int cc = (c + h) & 63;
            s += att[cc] * leaky(xr[cc] + xl[cc]);
        }
        float m = s;
        m = fmaxf(m, __shfl_xor_sync(0xffffffffu, m, 4));
        m = fmaxf(m, __shfl_xor_sync(0xffffffffu, m, 8));
        m = fmaxf(m, __shfl_xor_sync(0xffffffffu, m, 16));
        float e = __expf(s - m);
        float sum = e;
        sum += __shfl_xor_sync(0xffffffffu, sum, 4);
        sum += __shfl_xor_sync(0xffffffffu, sum, 8);
        sum += __shfl_xor_sync(0xffffffffu, sum, 16);
        float beta = e / sum;
        betaS[(node * 8 + r) * 4 + h] = beta;
        outBeta[(size_t)(g * 8 + node) * 32 + r * 4 + h] = beta;
    }
    __syncthreads();

    // Phase 7: out = relu(beta @ xl1 + bias1)
    {
        int h = col >> 6;
        float b1 = bias1[col];
#pragma unroll
        for (int nn = 0; nn < 4; nn++) {
            int nd = half * 4 + nn;
            float s = b1;
#pragma unroll
            for (int r = 0; r < 8; r++)
                s += betaS[(nd * 8 + r) * 4 + h] * bufXL[(nd * 8 + r) * PITCH + col];
            outEmb[(size_t)(g * 8 + nd) * 256 + col] = fmaxf(s, 0.f);
        }
    }
}

extern "C" void kernel_launch(void* const* d_in, const int* in_sizes, int n_in,
                              void* d_out, int out_size)
{
    const float* x     = (const float*)d_in[0];
    const float* Wl0   = (const float*)d_in[1];
    const float* bl0   = (const float*)d_in[2];
    const float* Wr0   = (const float*)d_in[3];
    const float* br0   = (const float*)d_in[4];
    const float* att0  = (const float*)d_in[5];
    const float* bias0 = (const float*)d_in[6];
    const float* Wl1   = (const float*)d_in[7];
    const float* bl1   = (const float*)d_in[8];
    const float* Wr1   = (const float*)d_in[9];
    const float* br1   = (const float*)d_in[10];
    const float* att1  = (const float*)d_in[11];
    const float* bias1 = (const float*)d_in[12];

    int nodes = in_sizes[0] / (RREL * EMBED);
    float* outEmb  = (float*)d_out;
    float* outBeta = outEmb + (size_t)nodes * EMBED;

    repack_W<<<256, 256>>>(Wl0, Wr0, Wl1, Wr1);

    size_t smem_bytes = (size_t)(3 * ROWS * PITCH + 2 * SLICE_F4 * 4 + 256 + 512)
                        * sizeof(float);
    cudaFuncSetAttribute(metapath_gat_kernel,
                         cudaFuncAttributeMaxDynamicSharedMemorySize,
                         (int)smem_bytes);

    metapath_gat_kernel<<<nodes / NB, NTHREADS, smem_bytes>>>(
        x, bl0, br0, att0, bias0, bl1, br1, att1, bias1, outEmb, outBeta);
}

// round 9
// speedup vs baseline: 5.2429x; 1.4426x over previous
#include <cuda_runtime.h>
#include <cstdint>

// MetapathGATConv fused kernel, R5: barrier-free streamed-W tf32 GEMMs
// (Wl+Wr both LDG.128 from L2, 1-slice register prefetch), i-blocked logits.

#define RREL   8
#define EMBED  256
#define NB     8
#define ROWS   64
#define PITCH  260
#define NTHREADS 512
#define KSTEPS 32
#define SLICE_F4 512
#define WMAT_F4 (KSTEPS * SLICE_F4)

__device__ float4 g_Wf[4 * WMAT_F4];   // Wl0 | Wr0 | Wl1 | Wr1, fragment-major tf32

__device__ __forceinline__ float tf32r(float x) {
    uint32_t u;
    asm("cvt.rna.tf32.f32 %0, %1;" : "=r"(u) : "f"(x));
    return __uint_as_float(u);
}
__device__ __forceinline__ float leaky(float v) { return v > 0.f ? v : 0.2f * v; }

__device__ __forceinline__ void mma_tf32(float* c, const uint32_t* a, const uint32_t* b) {
    asm volatile(
        "mma.sync.aligned.m16n8k8.row.col.f32.tf32.tf32.f32 "
        "{%0,%1,%2,%3}, {%4,%5,%6,%7}, {%8,%9}, {%0,%1,%2,%3};"
        : "+f"(c[0]), "+f"(c[1]), "+f"(c[2]), "+f"(c[3])
        : "r"(a[0]), "r"(a[1]), "r"(a[2]), "r"(a[3]), "r"(b[0]), "r"(b[1]));
}

// W repack: Wf[mat][s][grp][lane] fragment-major tf32.
__global__ void repack_W(const float* __restrict__ Wl0, const float* __restrict__ Wr0,
                         const float* __restrict__ Wl1, const float* __restrict__ Wr1)
{
    int idx = blockIdx.x * blockDim.x + threadIdx.x;
    int m   = idx >> 14;
    int rem = idx & 16383;
    int s   = rem >> 9;
    int g   = (rem >> 5) & 15;
    int l   = rem & 31;
    const float* W = (m == 0) ? Wl0 : (m == 1) ? Wr0 : (m == 2) ? Wl1 : Wr1;
    int k0 = 8 * s + (l & 3);
    int n0 = 16 * g + (l >> 2);
    float4 f;
    f.x = tf32r(W[k0 * EMBED + n0]);
    f.y = tf32r(W[(k0 + 4) * EMBED + n0]);
    f.z = tf32r(W[k0 * EMBED + n0 + 8]);
    f.w = tf32r(W[(k0 + 4) * EMBED + n0 + 8]);
    g_Wf[idx] = f;
}

// Fused dual GEMM, barrier-free: both Wl and Wr streamed from L2 with a
// one-slice register prefetch. DL = A@Wl + biasL; DR = A@Wr + biasR.
// SMALL: Wr path computes only rows node*8+7 (warps 0..7).
template <bool SMALL>
__device__ __forceinline__ void gemm_dual(
    const float4* __restrict__ WlF, const float* __restrict__ biasL,
    const float4* __restrict__ WrF, const float* __restrict__ biasR,
    const float* __restrict__ A, float* __restrict__ DL, float* __restrict__ DR,
    int tid)
{
    const int wid = tid >> 5, lane = tid & 31;
    const int mb = wid >> 3, nb = wid & 7;
    const int qr = lane >> 2, qk = lane & 3;
    const bool doR = !SMALL || wid < 8;

    float accL[8][4];
    float accR[8][4];
#pragma unroll
    for (int t = 0; t < 8; t++)
#pragma unroll
        for (int j = 0; j < 4; j++) { accL[t][j] = 0.f; accR[t][j] = 0.f; }

    // prefetch slice 0 fragments
    float4 pl0 = WlF[(nb * 2 + 0) * 32 + lane];
    float4 pl1 = WlF[(nb * 2 + 1) * 32 + lane];
    float4 pr0 = make_float4(0.f, 0.f, 0.f, 0.f), pr1 = pr0;
    if (doR) {
        pr0 = WrF[(nb * 2 + 0) * 32 + lane];
        pr1 = WrF[(nb * 2 + 1) * 32 + lane];
    }

#pragma unroll 2
    for (int s = 0; s < KSTEPS; s++) {
        float4 cl0 = pl0, cl1 = pl1, cr0 = pr0, cr1 = pr1;
        if (s + 1 < KSTEPS) {
            const float4* Wn = WlF + (s + 1) * SLICE_F4;
            pl0 = Wn[(nb * 2 + 0) * 32 + lane];
            pl1 = Wn[(nb * 2 + 1) * 32 + lane];
            if (doR) {
                const float4* Wm = WrF + (s + 1) * SLICE_F4;
                pr0 = Wm[(nb * 2 + 0) * 32 + lane];
                pr1 = Wm[(nb * 2 + 1) * 32 + lane];
            }
        }

        // A fragments (shared by both matrices)
        uint32_t a[2][4];
#pragma unroll
        for (int mt = 0; mt < 2; mt++) {
            const float* Ar  = A + (mb * 32 + mt * 16 + qr) * PITCH + s * 8;
            const float* Ar8 = Ar + 8 * PITCH;
            a[mt][0] = __float_as_uint(Ar[qk]);
            a[mt][1] = __float_as_uint(Ar8[qk]);
            a[mt][2] = __float_as_uint(Ar[qk + 4]);
            a[mt][3] = __float_as_uint(Ar8[qk + 4]);
        }
        uint32_t as[4];
        if (SMALL) {
            const float* Ar = A + (qr * 8 + 7) * PITCH + s * 8;
            as[0] = __float_as_uint(Ar[qk]);
            as[2] = __float_as_uint(Ar[qk + 4]);
            as[1] = as[0]; as[3] = as[2];
        }

        // Wl mma
        {
            uint32_t b[4][2];
            b[0][0] = __float_as_uint(cl0.x); b[0][1] = __float_as_uint(cl0.y);
            b[1][0] = __float_as_uint(cl0.z); b[1][1] = __float_as_uint(cl0.w);
            b[2][0] = __float_as_uint(cl1.x); b[2][1] = __float_as_uint(cl1.y);
            b[3][0] = __float_as_uint(cl1.z); b[3][1] = __float_as_uint(cl1.w);
#pragma unroll
            for (int mt = 0; mt < 2; mt++)
#pragma unroll
                for (int nt = 0; nt < 4; nt++) mma_tf32(accL[mt * 4 + nt], a[mt], b[nt]);
        }
        // Wr mma
        if (doR) {
            uint32_t b[4][2];
            b[0][0] = __float_as_uint(cr0.x); b[0][1] = __float_as_uint(cr0.y);
            b[1][0] = __float_as_uint(cr0.z); b[1][1] = __float_as_uint(cr0.w);
            b[2][0] = __float_as_uint(cr1.x); b[2][1] = __float_as_uint(cr1.y);
            b[3][0] = __float_as_uint(cr1.z); b[3][1] = __float_as_uint(cr1.w);
            if (!SMALL) {
#pragma unroll
                for (int mt = 0; mt < 2; mt++)
#pragma unroll
                    for (int nt = 0; nt < 4; nt++) mma_tf32(accR[mt * 4 + nt], a[mt], b[nt]);
            } else {
#pragma unroll
                for (int nt = 0; nt < 4; nt++) mma_tf32(accR[nt], as, b[nt]);
            }
        }
    }

    // epilogue (caller issues __syncthreads after)
#pragma unroll
    for (int mt = 0; mt < 2; mt++)
#pragma unroll
        for (int nt = 0; nt < 4; nt++) {
            int row = mb * 32 + mt * 16 + qr;
            int c0  = nb * 32 + nt * 8 + 2 * qk;
            float bx = biasL[c0], by = biasL[c0 + 1];
            float* d = DL + row * PITCH + c0;
            d[0] = accL[mt * 4 + nt][0] + bx;
            d[1] = accL[mt * 4 + nt][1] + by;
            d[8 * PITCH]     = accL[mt * 4 + nt][2] + bx;
            d[8 * PITCH + 1] = accL[mt * 4 + nt][3] + by;
        }
    if (!SMALL) {
#pragma unroll
        for (int mt = 0; mt < 2; mt++)
#pragma unroll
            for (int nt = 0; nt < 4; nt++) {
                int row = mb * 32 + mt * 16 + qr;
                int c0  = nb * 32 + nt * 8 + 2 * qk;
                float bx = biasR[c0], by = biasR[c0 + 1];
                float* d = DR + row * PITCH + c0;
                d[0] = accR[mt * 4 + nt][0] + bx;
                d[1] = accR[mt * 4 + nt][1] + by;
                d[8 * PITCH]     = accR[mt * 4 + nt][2] + bx;
                d[8 * PITCH + 1] = accR[mt * 4 + nt][3] + by;
            }
    } else if (wid < 8) {
#pragma unroll
        for (int nt = 0; nt < 4; nt++) {
            int c0 = nb * 32 + nt * 8 + 2 * qk;
            float* d = DR + (qr * 8 + 7) * PITCH + c0;
            d[0] = accR[nt][0] + biasR[c0];
            d[1] = accR[nt][1] + biasR[c0 + 1];
        }
    }
}

extern "C" __global__ void __launch_bounds__(NTHREADS, 1)
metapath_gat_kernel(
    const float* __restrict__ x,
    const float* __restrict__ bl0, const float* __restrict__ br0,
    const float* __restrict__ att0, const float* __restrict__ bias0,
    const float* __restrict__ bl1, const float* __restrict__ br1,
    const float* __restrict__ att1, const float* __restrict__ bias1,
    float* __restrict__ outEmb, float* __restrict__ outBeta)
{
    extern __shared__ float smem[];
    float* bufH     = smem;                          // [64][260]
    float* bufXL    = bufH + ROWS * PITCH;           // [64][260]
    float* bufXR    = bufXL + ROWS * PITCH;          // [64][260]
    float* partialS = bufXR + ROWS * PITCH;          // [64][8][8] = 4096
    float* alphaS   = partialS + 4096;               // 2048
    float* betaS    = alphaS + 2048;                 // 256
    float* attS     = betaS + 256;                   // 512

    const int tid = threadIdx.x;
    const int g = blockIdx.x;
    const float* xg = x + (size_t)g * (NB * RREL * EMBED);

    if (tid < 512) attS[tid] = (tid < 256) ? att0[tid] : att1[tid - 256];

    // Phase 1: x -> relu -> tf32 -> bufH
#pragma unroll
    for (int i = 0; i < 8; i++) {
        int idx = tid + i * NTHREADS;
        float4 v = reinterpret_cast<const float4*>(xg)[idx];
        int f = idx * 4;
        int r = f >> 8;
        int d = f & 255;
        v.x = tf32r(fmaxf(v.x, 0.f)); v.y = tf32r(fmaxf(v.y, 0.f));
        v.z = tf32r(fmaxf(v.z, 0.f)); v.w = tf32r(fmaxf(v.w, 0.f));
        *reinterpret_cast<float4*>(&bufH[r * PITCH + d]) = v;
    }
    __syncthreads();

    // Phase 2: fused layer-0 GEMMs (barrier-free mainloop)
    gemm_dual<false>(g_Wf + 0 * WMAT_F4, bl0, g_Wf + 1 * WMAT_F4, br0,
                     bufH, bufXL, bufXR, tid);
    __syncthreads();

    const int col  = tid & 255;
    const int half = tid >> 8;

    // Phase 3A: partial logits, i-register-blocked.
    // warp = (node, c-half); lane = (j, h); s[8] accumulates all dst i.
    {
        int w = tid >> 5, lane = tid & 31;
        int nd = w & 7, ch = w >> 3;
        int j = lane >> 2, h = lane & 3;
        const float* att = attS + h * 64;
        const float* xl  = bufXL + (nd * 8 + j) * PITCH + h * 64;
        const float* xrb = bufXR + (nd * 8) * PITCH + h * 64;
        float sa[8];
#pragma unroll
        for (int i = 0; i < 8; i++) sa[i] = 0.f;
        int c0 = ch * 32;
#pragma unroll 4
        for (int c = c0; c < c0 + 32; c++) {
            int cc = (c + h) & 63;          // bank-rotation: conflict-free xl
            float xlv = xl[cc];
            float av  = att[cc];
#pragma unroll
            for (int i = 0; i < 8; i++) {
                float xrv = xrb[i * PITCH + cc];
                sa[i] += av * leaky(xrv + xlv);
            }
        }
#pragma unroll
        for (int i = 0; i < 8; i++)
            partialS[((nd * 8 + i) * 8 + j) * 8 + ch * 4 + h] = sa[i];
    }
    __syncthreads();

    // Phase 3B: combine halves + softmax over j -> alphaS (warps 0..7)
    if (tid < 256) {
        int w = tid >> 5, lane = tid & 31;
        int nd = w, j = lane >> 2, h = lane & 3;
#pragma unroll
        for (int i = 0; i < 8; i++) {
            int base = ((nd * 8 + i) * 8 + j) * 8;
            float s = partialS[base + h] + partialS[base + 4 + h];
            float m = s;
            m = fmaxf(m, __shfl_xor_sync(0xffffffffu, m, 4));
            m = fmaxf(m, __shfl_xor_sync(0xffffffffu, m, 8));
            m = fmaxf(m, __shfl_xor_sync(0xffffffffu, m, 16));
            float e = __expf(s - m);
            float sum = e;
            sum += __shfl_xor_sync(0xffffffffu, sum, 4);
            sum += __shfl_xor_sync(0xffffffffu, sum, 8);
            sum += __shfl_xor_sync(0xffffffffu, sum, 16);
            alphaS[((nd * 8 + i) * 8 + j) * 4 + h] = e / sum;
        }
    }
    __syncthreads();

    // Phase 4: h1 = relu(alpha @ xl0 + bias0) -> bufH (tf32)
    {
        int h = col >> 6;
        float b0 = bias0[col];
#pragma unroll
        for (int nn = 0; nn < 4; nn++) {
            int nd = half * 4 + nn;
            float xlv[8];
#pragma unroll
            for (int j = 0; j < 8; j++) xlv[j] = bufXL[(nd * 8 + j) * PITCH + col];
#pragma unroll
            for (int i = 0; i < 8; i++) {
                float s = b0;
#pragma unroll
                for (int j = 0; j < 8; j++)
                    s += alphaS[((nd * 8 + i) * 8 + j) * 4 + h] * xlv[j];
                bufH[(nd * 8 + i) * PITCH + col] = tf32r(fmaxf(s, 0.f));
            }
        }
    }
    __syncthreads();

    // Phase 5: fused layer-1 GEMMs (xl1 full; xr1 self-rows)
    gemm_dual<true>(g_Wf + 2 * WMAT_F4, bl1, g_Wf + 3 * WMAT_F4, br1,
                    bufH, bufXL, bufXR, tid);
    __syncthreads();

    // Phase 6: logits1 + softmax over r -> beta
    if (tid < 256) {
        int node = tid >> 5, lane = tid & 31;
        int r = lane >> 2, h = lane & 3;
        const float* att = attS + 256 + h * 64;
        const float* xr = bufXR + (node * 8 + 7) * PITCH + h * 64;
        const float* xl = bufXL + (node * 8 + r) * PITCH + h * 64;
        float s = 0.f;
#pragma unroll 8
        for (int c = 0; c < 64; c++) {
            int cc = (c + h) & 63;
            s += att[cc] * leaky(xr[cc] + xl[cc]);
        }
        float m = s;
        m = fmaxf(m, __shfl_xor_sync(0xffffffffu, m, 4));
        m = fmaxf(m, __shfl_xor_sync(0xffffffffu, m, 8));
        m = fmaxf(m, __shfl_xor_sync(0xffffffffu, m, 16));
        float e = __expf(s - m);
        float sum = e;
        sum += __shfl_xor_sync(0xffffffffu, sum, 4);
        sum += __shfl_xor_sync(0xffffffffu, sum, 8);
        sum += __shfl_xor_sync(0xffffffffu, sum, 16);
        float beta = e / sum;
        betaS[(node * 8 + r) * 4 + h] = beta;
        outBeta[(size_t)(g * 8 + node) * 32 + r * 4 + h] = beta;
    }
    __syncthreads();

    // Phase 7: out = relu(beta @ xl1 + bias1)
    {
        int h = col >> 6;
        float b1 = bias1[col];
#pragma unroll
        for (int nn = 0; nn < 4; nn++) {
            int nd = half * 4 + nn;
            float s = b1;
#pragma unroll
            for (int r = 0; r < 8; r++)
                s += betaS[(nd * 8 + r) * 4 + h] * bufXL[(nd * 8 + r) * PITCH + col];
            outEmb[(size_t)(g * 8 + nd) * 256 + col] = fmaxf(s, 0.f);
        }
    }
}

extern "C" void kernel_launch(void* const* d_in, const int* in_sizes, int n_in,
                              void* d_out, int out_size)
{
    const float* x     = (const float*)d_in[0];
    const float* Wl0   = (const float*)d_in[1];
    const float* bl0   = (const float*)d_in[2];
    const float* Wr0   = (const float*)d_in[3];
    const float* br0   = (const float*)d_in[4];
    const float* att0  = (const float*)d_in[5];
    const float* bias0 = (const float*)d_in[6];
    const float* Wl1   = (const float*)d_in[7];
    const float* bl1   = (const float*)d_in[8];
    const float* Wr1   = (const float*)d_in[9];
    const float* br1   = (const float*)d_in[10];
    const float* att1  = (const float*)d_in[11];
    const float* bias1 = (const float*)d_in[12];

    int nodes = in_sizes[0] / (RREL * EMBED);
    float* outEmb  = (float*)d_out;
    float* outBeta = outEmb + (size_t)nodes * EMBED;

    repack_W<<<256, 256>>>(Wl0, Wr0, Wl1, Wr1);

    size_t smem_bytes = (size_t)(3 * ROWS * PITCH + 4096 + 2048 + 256 + 512)
                        * sizeof(float);
    cudaFuncSetAttribute(metapath_gat_kernel,
                         cudaFuncAttributeMaxDynamicSharedMemorySize,
                         (int)smem_bytes);

    metapath_gat_kernel<<<nodes / NB, NTHREADS, smem_bytes>>>(
        x, bl0, br0, att0, bias0, bl1, br1, att1, bias1, outEmb, outBeta);
}